// round 3
// baseline (speedup 1.0000x reference)
#include <cuda_runtime.h>
#include <cuda_bf16.h>
#include <math.h>

// Shapes
#define B_  1024
#define K_  32
#define G_  1024
#define ND_ 128   // NODE_DIM
#define ED_ 128   // EDGE_DIM
#define TD_ 100   // TIME_DIM
#define CD_ 228   // ED_+TD_
#define SD_ 356   // CD_+ND_  (acc_e | acc_t | out_node)

// Scratch (static device arrays — no allocation)
__device__ float g_S[B_ * SD_];        // per-b reduced vectors
__device__ float g_Wcat[SD_ * ND_];    // [0:228) = W_edge @ Wn_top ; [228:356) = Wn_bot
__device__ float g_cvec[ND_];          // constant output offset

// ---------------------------------------------------------------------------
// Kernel 0: fold weights.  Wc[i,e] = sum_j W_edge[i,j]*W_node[j,e];
// rows 228..355 copy W_node[128+j]; block 356 computes cvec.
// ---------------------------------------------------------------------------
__global__ __launch_bounds__(128) void prep_kernel(
    const float* __restrict__ W_edge, const float* __restrict__ b_edge,
    const float* __restrict__ w_final, const float* __restrict__ b_final,
    const float* __restrict__ W_node, const float* __restrict__ b_node)
{
    int i = blockIdx.x;
    int e = threadIdx.x;
    if (i < CD_) {
        __shared__ float row[128];
        row[e] = W_edge[i * 128 + e];
        __syncthreads();
        float acc = 0.f;
        #pragma unroll 8
        for (int j = 0; j < 128; ++j)
            acc += row[j] * W_node[j * 128 + e];
        g_Wcat[i * 128 + e] = acc;
    } else if (i < SD_) {
        g_Wcat[i * 128 + e] = W_node[(i - CD_ + 128) * 128 + e];
    } else {
        float sw = 0.f;
        #pragma unroll
        for (int k = 0; k < K_; ++k) sw += w_final[k];
        float bf = b_final[0];
        float acc = b_node[e];
        #pragma unroll 4
        for (int j = 0; j < 128; ++j)
            acc += (sw * b_edge[j] + bf) * W_node[j * 128 + e];
        g_cvec[e] = acc;
    }
}

// ---------------------------------------------------------------------------
// Kernel 1: per-b gathers + reductions.  Dominant kernel (L2-bound gather).
//  - node branch: sum of node_raw rows where id>0, plus count  (G=1024 rows)
//  - edge branch: w_final-weighted sum of edge_raw rows        (K=32 rows)
//  - time branch: acc_t[t] = sum_k maskw_k * cos(dt_k * w_t + b_t)
// ---------------------------------------------------------------------------
__global__ __launch_bounds__(256) void reduce_kernel(
    const int*   __restrict__ node_ids,
    const float* __restrict__ node_it,       // node_interact_times
    const int*   __restrict__ nbr_nid,       // neighbor_node_ids
    const int*   __restrict__ nbr_eid,       // neighbor_edge_ids
    const float* __restrict__ nbr_t,         // neighbor_times
    const int*   __restrict__ tg_ids,        // time_gap_neighbor_node_ids
    const float* __restrict__ node_raw,
    const float* __restrict__ edge_raw,
    const float* __restrict__ time_w,
    const float* __restrict__ time_b,
    const float* __restrict__ w_final)
{
    const int b    = blockIdx.x;
    const int tid  = threadIdx.x;
    const int w    = tid >> 5;
    const int lane = tid & 31;

    __shared__ float s_node[8 * 128];
    __shared__ float s_edge[8 * 128];
    __shared__ float s_dt[K_];
    __shared__ float s_wm[K_];
    __shared__ int   s_cnt;
    if (tid == 0) s_cnt = 0;
    __syncthreads();

    const float4* nf4 = (const float4*)node_raw;
    const float4* ef4 = (const float4*)edge_raw;

    // ---- node gather: warp w handles contiguous rows [w*128, w*128+128) ----
    {
        const int* tgb = tg_ids + b * G_;
        float4 acc = make_float4(0.f, 0.f, 0.f, 0.f);
        int cnt = 0;
        int base = w * 128;
        for (int c = 0; c < 4; ++c) {
            int myid = tgb[base + c * 32 + lane];          // coalesced 32 ids
            unsigned ball = __ballot_sync(0xffffffffu, myid > 0);
            cnt += __popc(ball);
            #pragma unroll 8
            for (int r = 0; r < 32; ++r) {
                int id  = __shfl_sync(0xffffffffu, myid, r);
                float m = (id > 0) ? 1.f : 0.f;            // rare zero: load row0, mult by 0
                float4 v = nf4[(size_t)id * 32 + lane];
                acc.x += m * v.x; acc.y += m * v.y;
                acc.z += m * v.z; acc.w += m * v.w;
            }
        }
        ((float4*)s_node)[w * 32 + lane] = acc;
        if (lane == 0) atomicAdd(&s_cnt, cnt);
    }

    // ---- edge gather: warp w handles rows [w*4, w*4+4) ----
    {
        float4 acc = make_float4(0.f, 0.f, 0.f, 0.f);
        #pragma unroll
        for (int q = 0; q < 4; ++q) {
            int k   = w * 4 + q;
            int eid = nbr_eid[b * K_ + k];
            float wk = w_final[k];
            float4 v = ef4[(size_t)eid * 32 + lane];
            acc.x += wk * v.x; acc.y += wk * v.y;
            acc.z += wk * v.z; acc.w += wk * v.w;
        }
        ((float4*)s_edge)[w * 32 + lane] = acc;
    }

    // dt / masked weight per neighbor
    if (tid < K_) {
        float dt = node_it[b] - nbr_t[b * K_ + tid];
        s_dt[tid] = dt;
        s_wm[tid] = (nbr_nid[b * K_ + tid] == 0) ? 0.f : w_final[tid];
    }
    __syncthreads();

    float* Sb = g_S + (size_t)b * SD_;
    if (tid < 128) {
        float a = 0.f, e = 0.f;
        #pragma unroll
        for (int q = 0; q < 8; ++q) {
            a += s_node[q * 128 + tid];
            e += s_edge[q * 128 + tid];
        }
        int c = s_cnt;
        float agg;
        if (c > 0) agg = a * (1.f / 1024.f) / (float)c;      // scores = 1/c exactly
        else       agg = node_raw[tid] * (1.f / 1024.f);     // all-masked degenerate case
        float outn = agg + node_raw[(size_t)node_ids[b] * 128 + tid];
        Sb[CD_ + tid] = outn;   // out_node -> [228:356)
        Sb[tid]       = e;      // weighted edge feats -> [0:128)
    } else if (tid < 128 + TD_) {
        int t = tid - 128;
        float wt = time_w[t], bt = time_b[t];
        float acc = 0.f;
        #pragma unroll
        for (int k = 0; k < K_; ++k)
            acc += s_wm[k] * cosf(fmaf(s_dt[k], wt, bt));
        Sb[128 + t] = acc;      // weighted time feats -> [128:228)
    }
}

// ---------------------------------------------------------------------------
// Kernel 2: out[b,e] = cvec[e] + sum_i S[b,i]*Wcat[i,e]
// Block handles 8 b-rows; thread = output column e. Wcat reused from L2.
// ---------------------------------------------------------------------------
__global__ __launch_bounds__(128) void final_kernel(float* __restrict__ out)
{
    const int b0 = blockIdx.x * 8;
    const int e  = threadIdx.x;

    __shared__ float s[8 * SD_];   // 8 rows of S (356 floats each, 16B-aligned rows)
    const float* Sg = g_S + (size_t)b0 * SD_;
    for (int idx = e; idx < 8 * SD_; idx += 128) s[idx] = Sg[idx];
    __syncthreads();

    float c0 = g_cvec[e];
    float acc[8];
    #pragma unroll
    for (int t = 0; t < 8; ++t) acc[t] = c0;

    for (int i = 0; i < SD_; i += 4) {
        float w0 = g_Wcat[(i + 0) * 128 + e];
        float w1 = g_Wcat[(i + 1) * 128 + e];
        float w2 = g_Wcat[(i + 2) * 128 + e];
        float w3 = g_Wcat[(i + 3) * 128 + e];
        #pragma unroll
        for (int t = 0; t < 8; ++t) {
            float4 sv = *(const float4*)&s[t * SD_ + i];
            acc[t] += sv.x * w0 + sv.y * w1 + sv.z * w2 + sv.w * w3;
        }
    }
    #pragma unroll
    for (int t = 0; t < 8; ++t)
        out[(size_t)(b0 + t) * 128 + e] = acc[t];
}

// ---------------------------------------------------------------------------
extern "C" void kernel_launch(void* const* d_in, const int* in_sizes, int n_in,
                              void* d_out, int out_size)
{
    const int*   node_ids = (const int*)  d_in[0];
    const float* node_it  = (const float*)d_in[1];
    const int*   nbr_nid  = (const int*)  d_in[2];
    const int*   nbr_eid  = (const int*)  d_in[3];
    const float* nbr_t    = (const float*)d_in[4];
    const int*   tg_ids   = (const int*)  d_in[5];
    const float* node_raw = (const float*)d_in[6];
    const float* edge_raw = (const float*)d_in[7];
    const float* time_w   = (const float*)d_in[8];
    const float* time_b   = (const float*)d_in[9];
    const float* W_edge   = (const float*)d_in[10];
    const float* b_edge   = (const float*)d_in[11];
    const float* w_final  = (const float*)d_in[12];
    const float* b_final  = (const float*)d_in[13];
    const float* W_node   = (const float*)d_in[14];
    const float* b_node   = (const float*)d_in[15];
    float* out = (float*)d_out;

    prep_kernel<<<SD_ + 1, 128>>>(W_edge, b_edge, w_final, b_final, W_node, b_node);
    reduce_kernel<<<B_, 256>>>(node_ids, node_it, nbr_nid, nbr_eid, nbr_t, tg_ids,
                               node_raw, edge_raw, time_w, time_b, w_final);
    final_kernel<<<B_ / 8, 128>>>(out);
}

// round 4
// speedup vs baseline: 1.0905x; 1.0905x over previous
#include <cuda_runtime.h>
#include <cuda_bf16.h>
#include <math.h>

// Shapes
#define B_  1024
#define K_  32
#define G_  1024
#define ND_ 128   // NODE_DIM
#define ED_ 128   // EDGE_DIM
#define TD_ 100   // TIME_DIM
#define CD_ 228   // ED_+TD_
#define SD_ 356   // CD_+ND_  (acc_e | acc_t | out_node)

// Scratch (static device arrays — no allocation)
__device__ __align__(16) float g_S[B_ * SD_];     // per-b reduced vectors
__device__ __align__(16) float g_Wcat[SD_ * ND_]; // [0:228)=W_edge@Wn_top ; [228:356)=Wn_bot
__device__ __align__(16) float g_cvec[ND_];       // constant output offset

// ---------------------------------------------------------------------------
// Kernel 0: fold weights.  Wc[i,e] = sum_j W_edge[i,j]*W_node[j,e].
// Blocks 0..56: 4 Wc rows each (4-row ILP so one W_node load feeds 4 FMA chains).
// Blocks 57..72: copy 8 rows of W_node bottom each. Block 73: cvec.
// ---------------------------------------------------------------------------
__global__ __launch_bounds__(128) void prep_kernel(
    const float* __restrict__ W_edge, const float* __restrict__ b_edge,
    const float* __restrict__ w_final, const float* __restrict__ b_final,
    const float* __restrict__ W_node, const float* __restrict__ b_node)
{
    const int blk = blockIdx.x;
    const int e   = threadIdx.x;
    if (blk < 57) {
        __shared__ float we[4][128];
        const int i0 = blk * 4;
        #pragma unroll
        for (int r = 0; r < 4; ++r)
            we[r][e] = W_edge[(i0 + r) * 128 + e];
        __syncthreads();
        float a0 = 0.f, a1 = 0.f, a2 = 0.f, a3 = 0.f;
        #pragma unroll 8
        for (int j = 0; j < 128; ++j) {
            float wn = __ldg(&W_node[j * 128 + e]);
            a0 = fmaf(we[0][j], wn, a0);
            a1 = fmaf(we[1][j], wn, a1);
            a2 = fmaf(we[2][j], wn, a2);
            a3 = fmaf(we[3][j], wn, a3);
        }
        g_Wcat[(i0 + 0) * 128 + e] = a0;
        g_Wcat[(i0 + 1) * 128 + e] = a1;
        g_Wcat[(i0 + 2) * 128 + e] = a2;
        g_Wcat[(i0 + 3) * 128 + e] = a3;
    } else if (blk < 73) {
        const int r0 = (blk - 57) * 8;
        #pragma unroll
        for (int r = 0; r < 8; ++r)
            g_Wcat[(CD_ + r0 + r) * 128 + e] = W_node[(128 + r0 + r) * 128 + e];
    } else {
        float sw = 0.f;
        #pragma unroll
        for (int k = 0; k < K_; ++k) sw += w_final[k];
        const float bf = b_final[0];
        float acc = b_node[e];
        #pragma unroll 8
        for (int j = 0; j < 128; ++j)
            acc = fmaf(fmaf(sw, b_edge[j], bf), __ldg(&W_node[j * 128 + e]), acc);
        g_cvec[e] = acc;
    }
}

// ---------------------------------------------------------------------------
// Kernel 1: per-b gathers + reductions.  Dominant (LTS-bound: 512 MB gather).
// ---------------------------------------------------------------------------
__global__ __launch_bounds__(256) void reduce_kernel(
    const int*   __restrict__ node_ids,
    const float* __restrict__ node_it,
    const int*   __restrict__ nbr_nid,
    const int*   __restrict__ nbr_eid,
    const float* __restrict__ nbr_t,
    const int*   __restrict__ tg_ids,
    const float* __restrict__ node_raw,
    const float* __restrict__ edge_raw,
    const float* __restrict__ time_w,
    const float* __restrict__ time_b,
    const float* __restrict__ w_final)
{
    const int b    = blockIdx.x;
    const int tid  = threadIdx.x;
    const int w    = tid >> 5;
    const int lane = tid & 31;

    __shared__ float s_node[8 * 128];
    __shared__ float s_edge[8 * 128];
    __shared__ float s_dt[K_];
    __shared__ float s_wm[K_];
    __shared__ int   s_cnt;
    if (tid == 0) s_cnt = 0;
    __syncthreads();

    const float4* nf4 = (const float4*)node_raw;
    const float4* ef4 = (const float4*)edge_raw;

    // ---- node gather: warp w owns contiguous rows [w*128, w*128+128) ----
    {
        const int* tgb = tg_ids + b * G_ + w * 128;
        int myid[4];
        #pragma unroll
        for (int c = 0; c < 4; ++c)
            myid[c] = tgb[c * 32 + lane];            // coalesced, prefetched

        float4 acc = make_float4(0.f, 0.f, 0.f, 0.f);
        int cnt = 0;
        #pragma unroll
        for (int c = 0; c < 4; ++c) {
            cnt += __popc(__ballot_sync(0xffffffffu, myid[c] > 0));
            #pragma unroll 16
            for (int r = 0; r < 32; ++r) {
                int id  = __shfl_sync(0xffffffffu, myid[c], r);
                float m = (id > 0) ? 1.f : 0.f;      // rare id==0: load row0, *0
                float4 v = __ldg(&nf4[(size_t)id * 32 + lane]);
                acc.x = fmaf(m, v.x, acc.x);
                acc.y = fmaf(m, v.y, acc.y);
                acc.z = fmaf(m, v.z, acc.z);
                acc.w = fmaf(m, v.w, acc.w);
            }
        }
        ((float4*)s_node)[w * 32 + lane] = acc;
        if (lane == 0) atomicAdd(&s_cnt, cnt);
    }

    // ---- edge gather: warp w owns rows [w*4, w*4+4) ----
    {
        float4 acc = make_float4(0.f, 0.f, 0.f, 0.f);
        #pragma unroll
        for (int q = 0; q < 4; ++q) {
            int k   = w * 4 + q;
            int eid = nbr_eid[b * K_ + k];
            float wk = w_final[k];
            float4 v = __ldg(&ef4[(size_t)eid * 32 + lane]);
            acc.x = fmaf(wk, v.x, acc.x);
            acc.y = fmaf(wk, v.y, acc.y);
            acc.z = fmaf(wk, v.z, acc.z);
            acc.w = fmaf(wk, v.w, acc.w);
        }
        ((float4*)s_edge)[w * 32 + lane] = acc;
    }

    if (tid < K_) {
        s_dt[tid] = node_it[b] - nbr_t[b * K_ + tid];
        s_wm[tid] = (nbr_nid[b * K_ + tid] == 0) ? 0.f : w_final[tid];
    }
    __syncthreads();

    float* Sb = g_S + (size_t)b * SD_;
    if (tid < 128) {
        float a = 0.f, e = 0.f;
        #pragma unroll
        for (int q = 0; q < 8; ++q) {
            a += s_node[q * 128 + tid];
            e += s_edge[q * 128 + tid];
        }
        int c = s_cnt;
        float agg;
        if (c > 0) agg = a * (1.f / 1024.f) / (float)c;      // softmax -> exactly 1/c
        else       agg = node_raw[tid] * (1.f / 1024.f);     // all-masked degenerate case
        float outn = agg + node_raw[(size_t)node_ids[b] * 128 + tid];
        Sb[CD_ + tid] = outn;   // out_node -> [228:356)
        Sb[tid]       = e;      // weighted edge feats -> [0:128)
    } else if (tid < 128 + TD_) {
        int t = tid - 128;
        float wt = time_w[t], bt = time_b[t];
        float acc = 0.f;
        #pragma unroll
        for (int k = 0; k < K_; ++k)
            acc = fmaf(s_wm[k], cosf(fmaf(s_dt[k], wt, bt)), acc);
        Sb[128 + t] = acc;      // weighted time feats -> [128:228)
    }
}

// ---------------------------------------------------------------------------
// Kernel 2: out[b,e] = cvec[e] + sum_i S[b,i]*Wcat[i,e].
// Block = 8 b-rows, 256 threads: (e, half); halves split i into [0,180)/[180,356)
// and combine via shared — halves the exposed serial chain at 1 block/SM.
// ---------------------------------------------------------------------------
__global__ __launch_bounds__(256) void final_kernel(float* __restrict__ out)
{
    const int b0 = blockIdx.x * 8;
    const int e  = threadIdx.x & 127;
    const int h  = threadIdx.x >> 7;

    __shared__ float s[8 * SD_];
    __shared__ float part[8][128];
    const float4* Sg4 = (const float4*)(g_S + (size_t)b0 * SD_);
    for (int idx = threadIdx.x; idx < 8 * SD_ / 4; idx += 256)
        ((float4*)s)[idx] = Sg4[idx];
    __syncthreads();

    const int i_beg = h ? 180 : 0;
    const int i_end = h ? SD_ : 180;

    float acc[8];
    #pragma unroll
    for (int t = 0; t < 8; ++t) acc[t] = 0.f;

    for (int i = i_beg; i < i_end; i += 4) {
        float w0 = g_Wcat[(i + 0) * 128 + e];
        float w1 = g_Wcat[(i + 1) * 128 + e];
        float w2 = g_Wcat[(i + 2) * 128 + e];
        float w3 = g_Wcat[(i + 3) * 128 + e];
        #pragma unroll
        for (int t = 0; t < 8; ++t) {
            float4 sv = *(const float4*)&s[t * SD_ + i];
            acc[t] += sv.x * w0 + sv.y * w1 + sv.z * w2 + sv.w * w3;
        }
    }

    if (h) {
        #pragma unroll
        for (int t = 0; t < 8; ++t) part[t][e] = acc[t];
    }
    __syncthreads();
    if (!h) {
        float c0 = g_cvec[e];
        #pragma unroll
        for (int t = 0; t < 8; ++t)
            out[(size_t)(b0 + t) * 128 + e] = c0 + acc[t] + part[t][e];
    }
}

// ---------------------------------------------------------------------------
extern "C" void kernel_launch(void* const* d_in, const int* in_sizes, int n_in,
                              void* d_out, int out_size)
{
    const int*   node_ids = (const int*)  d_in[0];
    const float* node_it  = (const float*)d_in[1];
    const int*   nbr_nid  = (const int*)  d_in[2];
    const int*   nbr_eid  = (const int*)  d_in[3];
    const float* nbr_t    = (const float*)d_in[4];
    const int*   tg_ids   = (const int*)  d_in[5];
    const float* node_raw = (const float*)d_in[6];
    const float* edge_raw = (const float*)d_in[7];
    const float* time_w   = (const float*)d_in[8];
    const float* time_b   = (const float*)d_in[9];
    const float* W_edge   = (const float*)d_in[10];
    const float* b_edge   = (const float*)d_in[11];
    const float* w_final  = (const float*)d_in[12];
    const float* b_final  = (const float*)d_in[13];
    const float* W_node   = (const float*)d_in[14];
    const float* b_node   = (const float*)d_in[15];
    float* out = (float*)d_out;

    prep_kernel<<<74, 128>>>(W_edge, b_edge, w_final, b_final, W_node, b_node);
    reduce_kernel<<<B_, 256>>>(node_ids, node_it, nbr_nid, nbr_eid, nbr_t, tg_ids,
                               node_raw, edge_raw, time_w, time_b, w_final);
    final_kernel<<<B_ / 8, 256>>>(out);
}

// round 5
// speedup vs baseline: 1.2890x; 1.1820x over previous
#include <cuda_runtime.h>
#include <cuda_bf16.h>
#include <math.h>

// Shapes
#define B_  1024
#define K_  32
#define G_  1024
#define ND_ 128   // NODE_DIM
#define ED_ 128   // EDGE_DIM
#define TD_ 100   // TIME_DIM
#define CD_ 228   // ED_+TD_
#define SD_ 356   // CD_+ND_  (acc_e | acc_t | out_node)

#define PREP_BLKS 74
#define GRID_MAIN (B_ + PREP_BLKS)

// Scratch (static device arrays — no allocation)
__device__ __align__(16) float g_S[B_ * SD_];     // per-b reduced vectors
__device__ __align__(16) float g_Wcat[SD_ * ND_]; // [0:228)=W_edge@Wn_top ; [228:356)=Wn_bot
__device__ __align__(16) float g_cvec[ND_];       // constant output offset

// ---------------------------------------------------------------------------
// Weight-fold work, run by the 74 trailing blocks of the main kernel (hidden
// behind the 1024 gather CTAs — zero critical-path cost).
// ---------------------------------------------------------------------------
__device__ __forceinline__ void prep_work(
    int blk, int e,
    const float* __restrict__ W_edge, const float* __restrict__ b_edge,
    const float* __restrict__ w_final, const float* __restrict__ b_final,
    const float* __restrict__ W_node, const float* __restrict__ b_node,
    float* s_we /* 4*128 shared */)
{
    if (blk < 57) {
        const int i0 = blk * 4;
        #pragma unroll
        for (int r = 0; r < 4; ++r)
            s_we[r * 128 + e] = W_edge[(i0 + r) * 128 + e];
        __syncthreads();
        float a0 = 0.f, a1 = 0.f, a2 = 0.f, a3 = 0.f;
        #pragma unroll 8
        for (int j = 0; j < 128; ++j) {
            float wn = __ldg(&W_node[j * 128 + e]);
            a0 = fmaf(s_we[0 * 128 + j], wn, a0);
            a1 = fmaf(s_we[1 * 128 + j], wn, a1);
            a2 = fmaf(s_we[2 * 128 + j], wn, a2);
            a3 = fmaf(s_we[3 * 128 + j], wn, a3);
        }
        g_Wcat[(i0 + 0) * 128 + e] = a0;
        g_Wcat[(i0 + 1) * 128 + e] = a1;
        g_Wcat[(i0 + 2) * 128 + e] = a2;
        g_Wcat[(i0 + 3) * 128 + e] = a3;
    } else if (blk < 73) {
        const int r0 = (blk - 57) * 8;
        #pragma unroll
        for (int r = 0; r < 8; ++r)
            g_Wcat[(CD_ + r0 + r) * 128 + e] = W_node[(128 + r0 + r) * 128 + e];
    } else {
        float sw = 0.f;
        #pragma unroll
        for (int k = 0; k < K_; ++k) sw += w_final[k];
        const float bf = b_final[0];
        float acc = b_node[e];
        #pragma unroll 8
        for (int j = 0; j < 128; ++j)
            acc = fmaf(fmaf(sw, b_edge[j], bf), __ldg(&W_node[j * 128 + e]), acc);
        g_cvec[e] = acc;
    }
}

// ---------------------------------------------------------------------------
// Main kernel: blocks [0,1024) do per-b gathers+reductions (LTS-bound,
// 512 MB of node-row gather); blocks [1024,1098) do the weight fold.
// 128 threads/CTA so all 1024 gather CTAs are resident in ONE wave.
// ---------------------------------------------------------------------------
__global__ __launch_bounds__(128) void main_kernel(
    const int*   __restrict__ node_ids,
    const float* __restrict__ node_it,
    const int*   __restrict__ nbr_nid,
    const int*   __restrict__ nbr_eid,
    const float* __restrict__ nbr_t,
    const int*   __restrict__ tg_ids,
    const float* __restrict__ node_raw,
    const float* __restrict__ edge_raw,
    const float* __restrict__ time_w,
    const float* __restrict__ time_b,
    const float* __restrict__ w_final,
    const float* __restrict__ W_edge,
    const float* __restrict__ b_edge,
    const float* __restrict__ b_final,
    const float* __restrict__ W_node,
    const float* __restrict__ b_node)
{
    __shared__ float s_node[4 * 128];
    __shared__ float s_edge[4 * 128];
    __shared__ float s_dt[K_];
    __shared__ float s_wm[K_];
    __shared__ int   s_cnt;

    const int b   = blockIdx.x;
    const int tid = threadIdx.x;

    if (b >= B_) {   // trailing blocks: weight fold (reuses s_node as scratch)
        prep_work(b - B_, tid, W_edge, b_edge, w_final, b_final, W_node, b_node,
                  s_node);
        return;
    }

    const int w    = tid >> 5;
    const int lane = tid & 31;
    if (tid == 0) s_cnt = 0;
    if (tid < K_) {
        s_dt[tid] = node_it[b] - nbr_t[b * K_ + tid];
        s_wm[tid] = (nbr_nid[b * K_ + tid] == 0) ? 0.f : w_final[tid];
    }
    __syncthreads();

    const float4* nf4 = (const float4*)node_raw;
    const float4* ef4 = (const float4*)edge_raw;

    // ---- node gather: warp w owns contiguous rows [w*256, w*256+256) ----
    {
        const int* tgb = tg_ids + b * G_ + w * 256;
        int myid[8];
        #pragma unroll
        for (int c = 0; c < 8; ++c)
            myid[c] = tgb[c * 32 + lane];            // coalesced, prefetched

        float4 acc = make_float4(0.f, 0.f, 0.f, 0.f);
        int cnt = 0;
        #pragma unroll
        for (int c = 0; c < 8; ++c) {
            cnt += __popc(__ballot_sync(0xffffffffu, myid[c] > 0));
            #pragma unroll 16
            for (int r = 0; r < 32; ++r) {
                int id  = __shfl_sync(0xffffffffu, myid[c], r);
                float m = (id > 0) ? 1.f : 0.f;      // rare id==0: load row0, *0
                float4 v = __ldg(&nf4[(size_t)id * 32 + lane]);
                acc.x = fmaf(m, v.x, acc.x);
                acc.y = fmaf(m, v.y, acc.y);
                acc.z = fmaf(m, v.z, acc.z);
                acc.w = fmaf(m, v.w, acc.w);
            }
        }
        ((float4*)s_node)[w * 32 + lane] = acc;
        if (lane == 0) atomicAdd(&s_cnt, cnt);
    }

    // ---- edge gather: warp w owns rows [w*8, w*8+8) ----
    {
        float4 acc = make_float4(0.f, 0.f, 0.f, 0.f);
        #pragma unroll
        for (int q = 0; q < 8; ++q) {
            int k   = w * 8 + q;
            int eid = nbr_eid[b * K_ + k];
            float wk = w_final[k];
            float4 v = __ldg(&ef4[(size_t)eid * 32 + lane]);
            acc.x = fmaf(wk, v.x, acc.x);
            acc.y = fmaf(wk, v.y, acc.y);
            acc.z = fmaf(wk, v.z, acc.z);
            acc.w = fmaf(wk, v.w, acc.w);
        }
        ((float4*)s_edge)[w * 32 + lane] = acc;
    }
    __syncthreads();

    float* Sb = g_S + (size_t)b * SD_;
    // combine across the 4 warps
    {
        float a = 0.f, e = 0.f;
        #pragma unroll
        for (int q = 0; q < 4; ++q) {
            a += s_node[q * 128 + tid];
            e += s_edge[q * 128 + tid];
        }
        int c = s_cnt;
        float agg;
        if (c > 0) agg = a * (1.f / 1024.f) / (float)c;      // softmax -> exactly 1/c
        else       agg = node_raw[tid] * (1.f / 1024.f);     // all-masked degenerate case
        float outn = agg + node_raw[(size_t)node_ids[b] * 128 + tid];
        Sb[CD_ + tid] = outn;   // out_node -> [228:356)
        Sb[tid]       = e;      // weighted edge feats -> [0:128)
    }
    // time branch (cheap: 32 cosf per thread, threads 0..99)
    if (tid < TD_) {
        float wt = time_w[tid], bt = time_b[tid];
        float acc = 0.f;
        #pragma unroll
        for (int k = 0; k < K_; ++k)
            acc = fmaf(s_wm[k], cosf(fmaf(s_dt[k], wt, bt)), acc);
        Sb[128 + tid] = acc;    // weighted time feats -> [128:228)
    }
}

// ---------------------------------------------------------------------------
// Kernel 2: out[b,e] = cvec[e] + sum_i S[b,i]*Wcat[i,e].
// Block = 8 b-rows, 256 threads: halves split i into [0,180)/[180,356).
// ---------------------------------------------------------------------------
__global__ __launch_bounds__(256) void final_kernel(float* __restrict__ out)
{
    const int b0 = blockIdx.x * 8;
    const int e  = threadIdx.x & 127;
    const int h  = threadIdx.x >> 7;

    __shared__ float s[8 * SD_];
    __shared__ float part[8][128];
    const float4* Sg4 = (const float4*)(g_S + (size_t)b0 * SD_);
    for (int idx = threadIdx.x; idx < 8 * SD_ / 4; idx += 256)
        ((float4*)s)[idx] = Sg4[idx];
    __syncthreads();

    const int i_beg = h ? 180 : 0;
    const int i_end = h ? SD_ : 180;

    float acc[8];
    #pragma unroll
    for (int t = 0; t < 8; ++t) acc[t] = 0.f;

    for (int i = i_beg; i < i_end; i += 4) {
        float w0 = g_Wcat[(i + 0) * 128 + e];
        float w1 = g_Wcat[(i + 1) * 128 + e];
        float w2 = g_Wcat[(i + 2) * 128 + e];
        float w3 = g_Wcat[(i + 3) * 128 + e];
        #pragma unroll
        for (int t = 0; t < 8; ++t) {
            float4 sv = *(const float4*)&s[t * SD_ + i];
            acc[t] += sv.x * w0 + sv.y * w1 + sv.z * w2 + sv.w * w3;
        }
    }

    if (h) {
        #pragma unroll
        for (int t = 0; t < 8; ++t) part[t][e] = acc[t];
    }
    __syncthreads();
    if (!h) {
        float c0 = g_cvec[e];
        #pragma unroll
        for (int t = 0; t < 8; ++t)
            out[(size_t)(b0 + t) * 128 + e] = c0 + acc[t] + part[t][e];
    }
}

// ---------------------------------------------------------------------------
extern "C" void kernel_launch(void* const* d_in, const int* in_sizes, int n_in,
                              void* d_out, int out_size)
{
    const int*   node_ids = (const int*)  d_in[0];
    const float* node_it  = (const float*)d_in[1];
    const int*   nbr_nid  = (const int*)  d_in[2];
    const int*   nbr_eid  = (const int*)  d_in[3];
    const float* nbr_t    = (const float*)d_in[4];
    const int*   tg_ids   = (const int*)  d_in[5];
    const float* node_raw = (const float*)d_in[6];
    const float* edge_raw = (const float*)d_in[7];
    const float* time_w   = (const float*)d_in[8];
    const float* time_b   = (const float*)d_in[9];
    const float* W_edge   = (const float*)d_in[10];
    const float* b_edge   = (const float*)d_in[11];
    const float* w_final  = (const float*)d_in[12];
    const float* b_final  = (const float*)d_in[13];
    const float* W_node   = (const float*)d_in[14];
    const float* b_node   = (const float*)d_in[15];
    float* out = (float*)d_out;

    main_kernel<<<GRID_MAIN, 128>>>(node_ids, node_it, nbr_nid, nbr_eid, nbr_t,
                                    tg_ids, node_raw, edge_raw, time_w, time_b,
                                    w_final, W_edge, b_edge, b_final, W_node,
                                    b_node);
    final_kernel<<<B_ / 8, 256>>>(out);
}

// round 6
// speedup vs baseline: 1.4441x; 1.1203x over previous
#include <cuda_runtime.h>
#include <cuda_bf16.h>
#include <math.h>

// Shapes
#define B_  1024
#define K_  32
#define G_  1024
#define ND_ 128   // NODE_DIM
#define ED_ 128   // EDGE_DIM
#define TD_ 100   // TIME_DIM
#define CD_ 228   // ED_+TD_
#define SD_ 356   // CD_+ND_  (acc_e | acc_t | out_node)
#define SDP 384   // padded stride (12 x 32 uniform tiles)
#define TILE 32
#define NT  12    // SDP / TILE

#define PREP_BLKS 74
#define GRID_MAIN (B_ + PREP_BLKS)

// Scratch (static device arrays — zero-initialized, no allocation)
__device__ __align__(16) float g_S[B_ * SDP];      // per-b reduced vectors (pad zeroed)
__device__ __align__(16) float g_Wcat[SDP * ND_];  // [0:228)=W_edge@Wn_top ; [228:356)=Wn_bot ; pad=0
__device__ __align__(16) float g_cvec[ND_];        // constant output offset

// ---------------------------------------------------------------------------
// Weight-fold work, run by the 74 trailing blocks of the main kernel (hidden
// behind the 1024 gather CTAs — zero critical-path cost).
// ---------------------------------------------------------------------------
__device__ __forceinline__ void prep_work(
    int blk, int e,
    const float* __restrict__ W_edge, const float* __restrict__ b_edge,
    const float* __restrict__ w_final, const float* __restrict__ b_final,
    const float* __restrict__ W_node, const float* __restrict__ b_node,
    float* s_we /* 4*128 shared */)
{
    if (blk < 57) {
        const int i0 = blk * 4;
        #pragma unroll
        for (int r = 0; r < 4; ++r)
            s_we[r * 128 + e] = W_edge[(i0 + r) * 128 + e];
        __syncthreads();
        float a0 = 0.f, a1 = 0.f, a2 = 0.f, a3 = 0.f;
        #pragma unroll 8
        for (int j = 0; j < 128; ++j) {
            float wn = __ldg(&W_node[j * 128 + e]);
            a0 = fmaf(s_we[0 * 128 + j], wn, a0);
            a1 = fmaf(s_we[1 * 128 + j], wn, a1);
            a2 = fmaf(s_we[2 * 128 + j], wn, a2);
            a3 = fmaf(s_we[3 * 128 + j], wn, a3);
        }
        g_Wcat[(i0 + 0) * 128 + e] = a0;
        g_Wcat[(i0 + 1) * 128 + e] = a1;
        g_Wcat[(i0 + 2) * 128 + e] = a2;
        g_Wcat[(i0 + 3) * 128 + e] = a3;
    } else if (blk < 73) {
        const int r0 = (blk - 57) * 8;
        #pragma unroll
        for (int r = 0; r < 8; ++r)
            g_Wcat[(CD_ + r0 + r) * 128 + e] = W_node[(128 + r0 + r) * 128 + e];
    } else {
        float sw = 0.f;
        #pragma unroll
        for (int k = 0; k < K_; ++k) sw += w_final[k];
        const float bf = b_final[0];
        float acc = b_node[e];
        #pragma unroll 8
        for (int j = 0; j < 128; ++j)
            acc = fmaf(fmaf(sw, b_edge[j], bf), __ldg(&W_node[j * 128 + e]), acc);
        g_cvec[e] = acc;
        // zero Wcat pad rows (kept zero anyway by zero-init; cheap insurance)
        #pragma unroll
        for (int r = SD_; r < SDP; ++r)
            g_Wcat[r * 128 + e] = 0.f;
    }
}

// ---------------------------------------------------------------------------
// Main kernel: blocks [0,1024) do per-b gathers+reductions (LTS-bound,
// 512 MB of node-row gather); blocks [1024,1098) do the weight fold.
// ---------------------------------------------------------------------------
__global__ __launch_bounds__(128) void main_kernel(
    const int*   __restrict__ node_ids,
    const float* __restrict__ node_it,
    const int*   __restrict__ nbr_nid,
    const int*   __restrict__ nbr_eid,
    const float* __restrict__ nbr_t,
    const int*   __restrict__ tg_ids,
    const float* __restrict__ node_raw,
    const float* __restrict__ edge_raw,
    const float* __restrict__ time_w,
    const float* __restrict__ time_b,
    const float* __restrict__ w_final,
    const float* __restrict__ W_edge,
    const float* __restrict__ b_edge,
    const float* __restrict__ b_final,
    const float* __restrict__ W_node,
    const float* __restrict__ b_node)
{
    __shared__ float s_node[4 * 128];
    __shared__ float s_edge[4 * 128];
    __shared__ float s_dt[K_];
    __shared__ float s_wm[K_];
    __shared__ int   s_cnt;

    const int b   = blockIdx.x;
    const int tid = threadIdx.x;

    if (b >= B_) {   // trailing blocks: weight fold (reuses s_node as scratch)
        prep_work(b - B_, tid, W_edge, b_edge, w_final, b_final, W_node, b_node,
                  s_node);
        return;
    }

    const int w    = tid >> 5;
    const int lane = tid & 31;
    if (tid == 0) s_cnt = 0;
    if (tid < K_) {
        s_dt[tid] = node_it[b] - nbr_t[b * K_ + tid];
        s_wm[tid] = (nbr_nid[b * K_ + tid] == 0) ? 0.f : w_final[tid];
    }
    __syncthreads();

    const float4* nf4 = (const float4*)node_raw;
    const float4* ef4 = (const float4*)edge_raw;

    // ---- node gather: warp w owns contiguous rows [w*256, w*256+256) ----
    {
        const int* tgb = tg_ids + b * G_ + w * 256;
        int myid[8];
        #pragma unroll
        for (int c = 0; c < 8; ++c)
            myid[c] = tgb[c * 32 + lane];            // coalesced, prefetched

        float4 acc = make_float4(0.f, 0.f, 0.f, 0.f);
        int cnt = 0;
        #pragma unroll
        for (int c = 0; c < 8; ++c) {
            cnt += __popc(__ballot_sync(0xffffffffu, myid[c] > 0));
            #pragma unroll 16
            for (int r = 0; r < 32; ++r) {
                int id  = __shfl_sync(0xffffffffu, myid[c], r);
                float m = (id > 0) ? 1.f : 0.f;      // rare id==0: load row0, *0
                float4 v = __ldg(&nf4[(size_t)id * 32 + lane]);
                acc.x = fmaf(m, v.x, acc.x);
                acc.y = fmaf(m, v.y, acc.y);
                acc.z = fmaf(m, v.z, acc.z);
                acc.w = fmaf(m, v.w, acc.w);
            }
        }
        ((float4*)s_node)[w * 32 + lane] = acc;
        if (lane == 0) atomicAdd(&s_cnt, cnt);
    }

    // ---- edge gather: warp w owns rows [w*8, w*8+8) ----
    {
        float4 acc = make_float4(0.f, 0.f, 0.f, 0.f);
        #pragma unroll
        for (int q = 0; q < 8; ++q) {
            int k   = w * 8 + q;
            int eid = nbr_eid[b * K_ + k];
            float wk = w_final[k];
            float4 v = __ldg(&ef4[(size_t)eid * 32 + lane]);
            acc.x = fmaf(wk, v.x, acc.x);
            acc.y = fmaf(wk, v.y, acc.y);
            acc.z = fmaf(wk, v.z, acc.z);
            acc.w = fmaf(wk, v.w, acc.w);
        }
        ((float4*)s_edge)[w * 32 + lane] = acc;
    }
    __syncthreads();

    float* Sb = g_S + (size_t)b * SDP;
    // combine across the 4 warps
    {
        float a = 0.f, e = 0.f;
        #pragma unroll
        for (int q = 0; q < 4; ++q) {
            a += s_node[q * 128 + tid];
            e += s_edge[q * 128 + tid];
        }
        int c = s_cnt;
        float agg;
        if (c > 0) agg = a * (1.f / 1024.f) / (float)c;      // softmax -> exactly 1/c
        else       agg = node_raw[tid] * (1.f / 1024.f);     // all-masked degenerate case
        float outn = agg + node_raw[(size_t)node_ids[b] * 128 + tid];
        Sb[CD_ + tid] = outn;   // out_node -> [228:356)
        Sb[tid]       = e;      // weighted edge feats -> [0:128)
    }
    // time branch (threads 0..99); threads 100..127 zero the S pad
    if (tid < TD_) {
        float wt = time_w[tid], bt = time_b[tid];
        float acc = 0.f;
        #pragma unroll
        for (int k = 0; k < K_; ++k)
            acc = fmaf(s_wm[k], cosf(fmaf(s_dt[k], wt, bt)), acc);
        Sb[128 + tid] = acc;    // weighted time feats -> [128:228)
    } else {
        Sb[256 + tid] = 0.f;    // tid in [100,128) -> S[356..384) = 0
    }
}

// ---------------------------------------------------------------------------
// Kernel 2: out[b,e] = cvec[e] + sum_i S[b,i]*Wcat[i,e].
// Block = 8 b-rows, 256 threads (half h owns 4 b-rows). Wcat staged through
// shared in 32-row tiles with register-prefetch double buffering — no raw
// L2-latency exposure in the inner loop.
// ---------------------------------------------------------------------------
__global__ __launch_bounds__(256) void final_kernel(float* __restrict__ out)
{
    const int b0  = blockIdx.x * 8;
    const int tid = threadIdx.x;
    const int e   = tid & 127;
    const int h   = tid >> 7;

    __shared__ float sS[8 * SDP];             // 12 KB
    __shared__ float sW[2][TILE * 128];       // 2 x 16 KB

    // Stage S rows (8 x 384 floats = 768 float4, 3 per thread)
    const float4* Sg4 = (const float4*)(g_S + (size_t)b0 * SDP);
    float4* sS4 = (float4*)sS;
    #pragma unroll
    for (int k = 0; k < 3; ++k)
        sS4[tid + k * 256] = Sg4[tid + k * 256];

    // Prefetch Wcat tile 0 (32 rows x 128 = 1024 float4, 4 per thread)
    const float4* W4 = (const float4*)g_Wcat;
    {
        float4 r0 = W4[tid + 0 * 256];
        float4 r1 = W4[tid + 1 * 256];
        float4 r2 = W4[tid + 2 * 256];
        float4 r3 = W4[tid + 3 * 256];
        float4* dst = (float4*)sW[0];
        dst[tid + 0 * 256] = r0;
        dst[tid + 1 * 256] = r1;
        dst[tid + 2 * 256] = r2;
        dst[tid + 3 * 256] = r3;
    }

    float acc[4] = {0.f, 0.f, 0.f, 0.f};

    for (int t = 0; t < NT; ++t) {
        __syncthreads();   // sW[t&1] ready; previous buffer fully consumed

        // prefetch next tile into registers (no smem hazard)
        float4 rn0, rn1, rn2, rn3;
        if (t + 1 < NT) {
            const float4* src = W4 + (t + 1) * 1024;
            rn0 = src[tid + 0 * 256];
            rn1 = src[tid + 1 * 256];
            rn2 = src[tid + 2 * 256];
            rn3 = src[tid + 3 * 256];
        }

        // compute on current tile
        const float* wbuf  = sW[t & 1];
        const float* sbase = sS + (h * 4) * SDP + t * TILE;
        #pragma unroll
        for (int g = 0; g < 8; ++g) {
            const int i = g * 4;
            float w0 = wbuf[(i + 0) * 128 + e];
            float w1 = wbuf[(i + 1) * 128 + e];
            float w2 = wbuf[(i + 2) * 128 + e];
            float w3 = wbuf[(i + 3) * 128 + e];
            #pragma unroll
            for (int tt = 0; tt < 4; ++tt) {
                float4 sv = *(const float4*)(sbase + tt * SDP + i);
                acc[tt] = fmaf(sv.x, w0, acc[tt]);
                acc[tt] = fmaf(sv.y, w1, acc[tt]);
                acc[tt] = fmaf(sv.z, w2, acc[tt]);
                acc[tt] = fmaf(sv.w, w3, acc[tt]);
            }
        }

        // stash next tile
        if (t + 1 < NT) {
            float4* dst = (float4*)sW[(t + 1) & 1];
            dst[tid + 0 * 256] = rn0;
            dst[tid + 1 * 256] = rn1;
            dst[tid + 2 * 256] = rn2;
            dst[tid + 3 * 256] = rn3;
        }
    }

    const float c0 = g_cvec[e];
    #pragma unroll
    for (int tt = 0; tt < 4; ++tt)
        out[(size_t)(b0 + h * 4 + tt) * 128 + e] = c0 + acc[tt];
}

// ---------------------------------------------------------------------------
extern "C" void kernel_launch(void* const* d_in, const int* in_sizes, int n_in,
                              void* d_out, int out_size)
{
    const int*   node_ids = (const int*)  d_in[0];
    const float* node_it  = (const float*)d_in[1];
    const int*   nbr_nid  = (const int*)  d_in[2];
    const int*   nbr_eid  = (const int*)  d_in[3];
    const float* nbr_t    = (const float*)d_in[4];
    const int*   tg_ids   = (const int*)  d_in[5];
    const float* node_raw = (const float*)d_in[6];
    const float* edge_raw = (const float*)d_in[7];
    const float* time_w   = (const float*)d_in[8];
    const float* time_b   = (const float*)d_in[9];
    const float* W_edge   = (const float*)d_in[10];
    const float* b_edge   = (const float*)d_in[11];
    const float* w_final  = (const float*)d_in[12];
    const float* b_final  = (const float*)d_in[13];
    const float* W_node   = (const float*)d_in[14];
    const float* b_node   = (const float*)d_in[15];
    float* out = (float*)d_out;

    main_kernel<<<GRID_MAIN, 128>>>(node_ids, node_it, nbr_nid, nbr_eid, nbr_t,
                                    tg_ids, node_raw, edge_raw, time_w, time_b,
                                    w_final, W_edge, b_edge, b_final, W_node,
                                    b_node);
    final_kernel<<<B_ / 8, 256>>>(out);
}

// round 8
// speedup vs baseline: 1.4838x; 1.0275x over previous
#include <cuda_runtime.h>
#include <cuda_bf16.h>
#include <math.h>
#include <cstdint>

// Shapes
#define B_  1024
#define K_  32
#define G_  1024
#define ND_ 128   // NODE_DIM
#define ED_ 128   // EDGE_DIM
#define TD_ 100   // TIME_DIM
#define CD_ 228   // ED_+TD_
#define SD_ 356   // CD_+ND_  (acc_e | acc_t | out_node)
#define SDP 384   // padded stride
#define FT  16    // final-kernel tile rows
#define FNT 24    // SDP / FT
#define FST 4     // pipeline stages

#define PREP_BLKS 74
#define GRID_MAIN (B_ + PREP_BLKS)

// Scratch (static device arrays — zero-initialized, no allocation)
__device__ __align__(16) float g_S[B_ * SDP];      // per-b reduced vectors (pad zeroed)
__device__ __align__(16) float g_Wcat[SDP * ND_];  // [0:228)=W_edge@Wn_top ; [228:356)=Wn_bot ; pad=0
__device__ __align__(16) float g_cvec[ND_];        // constant output offset

// ---- cp.async helpers -----------------------------------------------------
__device__ __forceinline__ void cp16(void* smem_dst, const void* gsrc) {
    unsigned int s = (unsigned int)__cvta_generic_to_shared(smem_dst);
    asm volatile("cp.async.cg.shared.global [%0], [%1], 16;" :: "r"(s), "l"(gsrc));
}
#define CP_COMMIT() asm volatile("cp.async.commit_group;")
#define CP_WAIT2()  asm volatile("cp.async.wait_group 2;")

// ---------------------------------------------------------------------------
// Weight-fold work, run by the 74 trailing blocks of the main kernel (hidden
// behind the 1024 gather CTAs — zero critical-path cost).
// ---------------------------------------------------------------------------
__device__ __forceinline__ void prep_work(
    int blk, int e,
    const float* __restrict__ W_edge, const float* __restrict__ b_edge,
    const float* __restrict__ w_final, const float* __restrict__ b_final,
    const float* __restrict__ W_node, const float* __restrict__ b_node,
    float* s_we /* 4*128 shared */)
{
    if (blk < 57) {
        const int i0 = blk * 4;
        #pragma unroll
        for (int r = 0; r < 4; ++r)
            s_we[r * 128 + e] = W_edge[(i0 + r) * 128 + e];
        __syncthreads();
        float a0 = 0.f, a1 = 0.f, a2 = 0.f, a3 = 0.f;
        #pragma unroll 8
        for (int j = 0; j < 128; ++j) {
            float wn = __ldg(&W_node[j * 128 + e]);
            a0 = fmaf(s_we[0 * 128 + j], wn, a0);
            a1 = fmaf(s_we[1 * 128 + j], wn, a1);
            a2 = fmaf(s_we[2 * 128 + j], wn, a2);
            a3 = fmaf(s_we[3 * 128 + j], wn, a3);
        }
        g_Wcat[(i0 + 0) * 128 + e] = a0;
        g_Wcat[(i0 + 1) * 128 + e] = a1;
        g_Wcat[(i0 + 2) * 128 + e] = a2;
        g_Wcat[(i0 + 3) * 128 + e] = a3;
    } else if (blk < 73) {
        const int r0 = (blk - 57) * 8;
        #pragma unroll
        for (int r = 0; r < 8; ++r)
            g_Wcat[(CD_ + r0 + r) * 128 + e] = W_node[(128 + r0 + r) * 128 + e];
    } else {
        float sw = 0.f;
        #pragma unroll
        for (int k = 0; k < K_; ++k) sw += w_final[k];
        const float bf = b_final[0];
        float acc = b_node[e];
        #pragma unroll 8
        for (int j = 0; j < 128; ++j)
            acc = fmaf(fmaf(sw, b_edge[j], bf), __ldg(&W_node[j * 128 + e]), acc);
        g_cvec[e] = acc;
        #pragma unroll
        for (int r = SD_; r < SDP; ++r)       // keep pad rows zero
            g_Wcat[r * 128 + e] = 0.f;
    }
}

// ---------------------------------------------------------------------------
// Main kernel: blocks [0,1024) do per-b gathers+reductions (LTS-bound,
// 512 MB of node-row gather); blocks [1024,1098) do the weight fold.
// ---------------------------------------------------------------------------
__global__ __launch_bounds__(128) void main_kernel(
    const int*   __restrict__ node_ids,
    const float* __restrict__ node_it,
    const int*   __restrict__ nbr_nid,
    const int*   __restrict__ nbr_eid,
    const float* __restrict__ nbr_t,
    const int*   __restrict__ tg_ids,
    const float* __restrict__ node_raw,
    const float* __restrict__ edge_raw,
    const float* __restrict__ time_w,
    const float* __restrict__ time_b,
    const float* __restrict__ w_final,
    const float* __restrict__ W_edge,
    const float* __restrict__ b_edge,
    const float* __restrict__ b_final,
    const float* __restrict__ W_node,
    const float* __restrict__ b_node)
{
    __shared__ float s_node[4 * 128];
    __shared__ float s_edge[4 * 128];
    __shared__ float s_dt[K_];
    __shared__ float s_wm[K_];
    __shared__ int   s_cnt;

    const int b   = blockIdx.x;
    const int tid = threadIdx.x;

    if (b >= B_) {   // trailing blocks: weight fold (reuses s_node as scratch)
        prep_work(b - B_, tid, W_edge, b_edge, w_final, b_final, W_node, b_node,
                  s_node);
        return;
    }

    const int w    = tid >> 5;
    const int lane = tid & 31;
    if (tid == 0) s_cnt = 0;
    if (tid < K_) {
        s_dt[tid] = node_it[b] - nbr_t[b * K_ + tid];
        s_wm[tid] = (nbr_nid[b * K_ + tid] == 0) ? 0.f : w_final[tid];
    }
    __syncthreads();

    const float4* nf4 = (const float4*)node_raw;
    const float4* ef4 = (const float4*)edge_raw;

    // ---- node gather: warp w owns contiguous rows [w*256, w*256+256) ----
    {
        const int* tgb = tg_ids + b * G_ + w * 256;
        int myid[8];
        #pragma unroll
        for (int c = 0; c < 8; ++c)
            myid[c] = tgb[c * 32 + lane];            // coalesced, prefetched

        float4 acc = make_float4(0.f, 0.f, 0.f, 0.f);
        int cnt = 0;
        #pragma unroll
        for (int c = 0; c < 8; ++c) {
            cnt += __popc(__ballot_sync(0xffffffffu, myid[c] > 0));
            #pragma unroll 16
            for (int r = 0; r < 32; ++r) {
                int id  = __shfl_sync(0xffffffffu, myid[c], r);
                float m = (id > 0) ? 1.f : 0.f;      // rare id==0: load row0, *0
                float4 v = __ldg(&nf4[(size_t)id * 32 + lane]);
                acc.x = fmaf(m, v.x, acc.x);
                acc.y = fmaf(m, v.y, acc.y);
                acc.z = fmaf(m, v.z, acc.z);
                acc.w = fmaf(m, v.w, acc.w);
            }
        }
        ((float4*)s_node)[w * 32 + lane] = acc;
        if (lane == 0) atomicAdd(&s_cnt, cnt);
    }

    // ---- edge gather: warp w owns rows [w*8, w*8+8) ----
    {
        float4 acc = make_float4(0.f, 0.f, 0.f, 0.f);
        #pragma unroll
        for (int q = 0; q < 8; ++q) {
            int k   = w * 8 + q;
            int eid = nbr_eid[b * K_ + k];
            float wk = w_final[k];
            float4 v = __ldg(&ef4[(size_t)eid * 32 + lane]);
            acc.x = fmaf(wk, v.x, acc.x);
            acc.y = fmaf(wk, v.y, acc.y);
            acc.z = fmaf(wk, v.z, acc.z);
            acc.w = fmaf(wk, v.w, acc.w);
        }
        ((float4*)s_edge)[w * 32 + lane] = acc;
    }
    __syncthreads();

    float* Sb = g_S + (size_t)b * SDP;
    {
        float a = 0.f, e = 0.f;
        #pragma unroll
        for (int q = 0; q < 4; ++q) {
            a += s_node[q * 128 + tid];
            e += s_edge[q * 128 + tid];
        }
        int c = s_cnt;
        float agg;
        if (c > 0) agg = a * (1.f / 1024.f) / (float)c;      // softmax -> exactly 1/c
        else       agg = node_raw[tid] * (1.f / 1024.f);     // all-masked degenerate case
        float outn = agg + node_raw[(size_t)node_ids[b] * 128 + tid];
        Sb[CD_ + tid] = outn;   // out_node -> [228:356)
        Sb[tid]       = e;      // weighted edge feats -> [0:128)
    }
    if (tid < TD_) {
        float wt = time_w[tid], bt = time_b[tid];
        float acc = 0.f;
        #pragma unroll
        for (int k = 0; k < K_; ++k)
            acc = fmaf(s_wm[k], cosf(fmaf(s_dt[k], wt, bt)), acc);
        Sb[128 + tid] = acc;    // weighted time feats -> [128:228)
    } else {
        Sb[256 + tid] = 0.f;    // tid in [100,128) -> S[356..384) = 0
    }
}

// ---------------------------------------------------------------------------
// Kernel 2: out[b,e] = cvec[e] + sum_i S[b,i]*Wcat[i,e].
// Grid 256 x 4 b-rows. Wcat streamed via cp.async 4-stage pipeline of
// 16-row tiles (8 KB/stage) — L2 latency stays inside the pipeline; ~2 CTA/SM.
// ---------------------------------------------------------------------------
__global__ __launch_bounds__(256) void final_kernel(float* __restrict__ out)
{
    const int b0  = blockIdx.x * 4;
    const int tid = threadIdx.x;
    const int e   = tid & 127;
    const int h   = tid >> 7;        // half owns rows {2h, 2h+1}

    __shared__ float sW[FST][FT * 128];   // 4 x 8 KB
    __shared__ float sS[4 * SDP];         // 6 KB

    const float4* W4 = (const float4*)g_Wcat;

    // prologue: issue stages 0..2
    #pragma unroll
    for (int s = 0; s < FST - 1; ++s) {
        const float4* src = W4 + s * (FT * 32);          // FT*128/4 = 512 float4
        float4* dst = (float4*)sW[s];
        cp16(dst + tid,       src + tid);
        cp16(dst + tid + 256, src + tid + 256);
        CP_COMMIT();
    }

    // stage S rows (4 x 384 floats = 384 float4)
    {
        const float4* Sg4 = (const float4*)(g_S + (size_t)b0 * SDP);
        float4* d = (float4*)sS;
        d[tid] = Sg4[tid];
        if (tid < 128) d[tid + 256] = Sg4[tid + 256];
    }

    float acc0 = 0.f, acc1 = 0.f;
    const float* s0 = sS + (2 * h + 0) * SDP;
    const float* s1 = sS + (2 * h + 1) * SDP;

    for (int t = 0; t < FNT; ++t) {
        CP_WAIT2();
        __syncthreads();                 // stage t resident; stage t-1 consumed by all

        const float* wbuf = sW[t & (FST - 1)];
        const int ib = t * FT;
        #pragma unroll
        for (int g = 0; g < FT / 4; ++g) {
            const int i = g * 4;
            float w0 = wbuf[(i + 0) * 128 + e];
            float w1 = wbuf[(i + 1) * 128 + e];
            float w2 = wbuf[(i + 2) * 128 + e];
            float w3 = wbuf[(i + 3) * 128 + e];
            float4 a = *(const float4*)(s0 + ib + i);
            float4 b = *(const float4*)(s1 + ib + i);
            acc0 = fmaf(a.x, w0, acc0); acc1 = fmaf(b.x, w0, acc1);
            acc0 = fmaf(a.y, w1, acc0); acc1 = fmaf(b.y, w1, acc1);
            acc0 = fmaf(a.z, w2, acc0); acc1 = fmaf(b.z, w2, acc1);
            acc0 = fmaf(a.w, w3, acc0); acc1 = fmaf(b.w, w3, acc1);
        }

        const int tn = t + FST - 1;
        if (tn < FNT) {                  // refill buffer (t-1)%4 — safe post-sync
            const float4* src = W4 + tn * (FT * 32);
            float4* dst = (float4*)sW[tn & (FST - 1)];
            cp16(dst + tid,       src + tid);
            cp16(dst + tid + 256, src + tid + 256);
            CP_COMMIT();
        } else {
            CP_COMMIT();                 // keep group count uniform for wait_group
        }
    }

    const float c0 = g_cvec[e];
    out[(size_t)(b0 + 2 * h + 0) * 128 + e] = c0 + acc0;
    out[(size_t)(b0 + 2 * h + 1) * 128 + e] = c0 + acc1;
}

// ---------------------------------------------------------------------------
extern "C" void kernel_launch(void* const* d_in, const int* in_sizes, int n_in,
                              void* d_out, int out_size)
{
    const int*   node_ids = (const int*)  d_in[0];
    const float* node_it  = (const float*)d_in[1];
    const int*   nbr_nid  = (const int*)  d_in[2];
    const int*   nbr_eid  = (const int*)  d_in[3];
    const float* nbr_t    = (const float*)d_in[4];
    const int*   tg_ids   = (const int*)  d_in[5];
    const float* node_raw = (const float*)d_in[6];
    const float* edge_raw = (const float*)d_in[7];
    const float* time_w   = (const float*)d_in[8];
    const float* time_b   = (const float*)d_in[9];
    const float* W_edge   = (const float*)d_in[10];
    const float* b_edge   = (const float*)d_in[11];
    const float* w_final  = (const float*)d_in[12];
    const float* b_final  = (const float*)d_in[13];
    const float* W_node   = (const float*)d_in[14];
    const float* b_node   = (const float*)d_in[15];
    float* out = (float*)d_out;

    main_kernel<<<GRID_MAIN, 128>>>(node_ids, node_it, nbr_nid, nbr_eid, nbr_t,
                                    tg_ids, node_raw, edge_raw, time_w, time_b,
                                    w_final, W_edge, b_edge, b_final, W_node,
                                    b_node);
    final_kernel<<<B_ / 4, 256>>>(out);
}

// round 9
// speedup vs baseline: 1.5304x; 1.0314x over previous
#include <cuda_runtime.h>
#include <cuda_bf16.h>
#include <math.h>
#include <cstdint>

// Shapes
#define B_  1024
#define K_  32
#define G_  1024
#define ND_ 128
#define ED_ 128
#define TD_ 100
#define CD_ 228
#define SD_ 356
#define SDP 384   // padded stride; Wcat rows [356,384) are zero
#define FT2 16    // final tile i-rows
#define HNT 12    // tiles per i-half (192/16)
#define FST 3     // cp.async stages per half

#define PREP_BLKS 74
#define GRID_MAIN (B_ + PREP_BLKS)

// final-kernel dynamic smem layout (floats)
#define OFF_W   0         // [2][3][16*128] = 12288 floats
#define OFF_SP  12288     // [2][192][8]    = 3072 floats (row-interleaved S)
#define OFF_PART 15360    // [8][128]       = 1024 floats
#define FSMEM_BYTES (16384 * 4)

__device__ __align__(16) float g_S[B_ * SDP];
__device__ __align__(16) float g_Wcat[SDP * ND_];
__device__ __align__(16) float g_cvec[ND_];

typedef unsigned long long ull;

// ---- packed f32x2 helpers -------------------------------------------------
__device__ __forceinline__ ull fma2(ull a, ull b, ull c) {
    ull d;
    asm("fma.rn.f32x2 %0, %1, %2, %3;" : "=l"(d) : "l"(a), "l"(b), "l"(c));
    return d;
}
__device__ __forceinline__ ull pack2(float lo, float hi) {
    ull d;
    asm("mov.b64 %0, {%1, %2};" : "=l"(d)
        : "r"(__float_as_uint(lo)), "r"(__float_as_uint(hi)));
    return d;
}
__device__ __forceinline__ void unpack2(ull v, float& lo, float& hi) {
    unsigned int a, b;
    asm("mov.b64 {%0, %1}, %2;" : "=r"(a), "=r"(b) : "l"(v));
    lo = __uint_as_float(a); hi = __uint_as_float(b);
}
// ---- cp.async helpers -----------------------------------------------------
__device__ __forceinline__ void cp16(void* smem_dst, const void* gsrc) {
    unsigned int s = (unsigned int)__cvta_generic_to_shared(smem_dst);
    asm volatile("cp.async.cg.shared.global [%0], [%1], 16;" :: "r"(s), "l"(gsrc));
}
#define CP_COMMIT() asm volatile("cp.async.commit_group;")
#define CP_WAIT1()  asm volatile("cp.async.wait_group 1;")

// ---------------------------------------------------------------------------
// Weight fold — trailing blocks of the main launch (hidden behind gathers).
// ---------------------------------------------------------------------------
__device__ __forceinline__ void prep_work(
    int blk, int e,
    const float* __restrict__ W_edge, const float* __restrict__ b_edge,
    const float* __restrict__ w_final, const float* __restrict__ b_final,
    const float* __restrict__ W_node, const float* __restrict__ b_node,
    float* s_we)
{
    if (blk < 57) {
        const int i0 = blk * 4;
        #pragma unroll
        for (int r = 0; r < 4; ++r)
            s_we[r * 128 + e] = W_edge[(i0 + r) * 128 + e];
        __syncthreads();
        float a0 = 0.f, a1 = 0.f, a2 = 0.f, a3 = 0.f;
        #pragma unroll 8
        for (int j = 0; j < 128; ++j) {
            float wn = __ldg(&W_node[j * 128 + e]);
            a0 = fmaf(s_we[0 * 128 + j], wn, a0);
            a1 = fmaf(s_we[1 * 128 + j], wn, a1);
            a2 = fmaf(s_we[2 * 128 + j], wn, a2);
            a3 = fmaf(s_we[3 * 128 + j], wn, a3);
        }
        g_Wcat[(i0 + 0) * 128 + e] = a0;
        g_Wcat[(i0 + 1) * 128 + e] = a1;
        g_Wcat[(i0 + 2) * 128 + e] = a2;
        g_Wcat[(i0 + 3) * 128 + e] = a3;
    } else if (blk < 73) {
        const int r0 = (blk - 57) * 8;
        #pragma unroll
        for (int r = 0; r < 8; ++r)
            g_Wcat[(CD_ + r0 + r) * 128 + e] = W_node[(128 + r0 + r) * 128 + e];
    } else {
        float sw = 0.f;
        #pragma unroll
        for (int k = 0; k < K_; ++k) sw += w_final[k];
        const float bf = b_final[0];
        float acc = b_node[e];
        #pragma unroll 8
        for (int j = 0; j < 128; ++j)
            acc = fmaf(fmaf(sw, b_edge[j], bf), __ldg(&W_node[j * 128 + e]), acc);
        g_cvec[e] = acc;
        #pragma unroll
        for (int r = SD_; r < SDP; ++r)       // keep pad rows zero
            g_Wcat[r * 128 + e] = 0.f;
    }
}

// ---------------------------------------------------------------------------
// Main kernel: blocks [0,1024) gather+reduce (LTS-bound, 512 MB);
// blocks [1024,1098) fold weights.
// ---------------------------------------------------------------------------
__global__ __launch_bounds__(128) void main_kernel(
    const int*   __restrict__ node_ids,
    const float* __restrict__ node_it,
    const int*   __restrict__ nbr_nid,
    const int*   __restrict__ nbr_eid,
    const float* __restrict__ nbr_t,
    const int*   __restrict__ tg_ids,
    const float* __restrict__ node_raw,
    const float* __restrict__ edge_raw,
    const float* __restrict__ time_w,
    const float* __restrict__ time_b,
    const float* __restrict__ w_final,
    const float* __restrict__ W_edge,
    const float* __restrict__ b_edge,
    const float* __restrict__ b_final,
    const float* __restrict__ W_node,
    const float* __restrict__ b_node)
{
    __shared__ float s_node[4 * 128];
    __shared__ float s_edge[4 * 128];
    __shared__ float s_dt[K_];
    __shared__ float s_wm[K_];
    __shared__ int   s_cnt;

    const int b   = blockIdx.x;
    const int tid = threadIdx.x;

    if (b >= B_) {
        prep_work(b - B_, tid, W_edge, b_edge, w_final, b_final, W_node, b_node,
                  s_node);
        return;
    }

    const int w    = tid >> 5;
    const int lane = tid & 31;
    if (tid == 0) s_cnt = 0;
    if (tid < K_) {
        s_dt[tid] = node_it[b] - nbr_t[b * K_ + tid];
        s_wm[tid] = (nbr_nid[b * K_ + tid] == 0) ? 0.f : w_final[tid];
    }
    __syncthreads();

    const float4* nf4 = (const float4*)node_raw;
    const float4* ef4 = (const float4*)edge_raw;

    {   // node gather: warp w owns rows [w*256, w*256+256)
        const int* tgb = tg_ids + b * G_ + w * 256;
        int myid[8];
        #pragma unroll
        for (int c = 0; c < 8; ++c)
            myid[c] = tgb[c * 32 + lane];

        float4 acc = make_float4(0.f, 0.f, 0.f, 0.f);
        int cnt = 0;
        #pragma unroll
        for (int c = 0; c < 8; ++c) {
            cnt += __popc(__ballot_sync(0xffffffffu, myid[c] > 0));
            #pragma unroll 16
            for (int r = 0; r < 32; ++r) {
                int id  = __shfl_sync(0xffffffffu, myid[c], r);
                float m = (id > 0) ? 1.f : 0.f;
                float4 v = __ldg(&nf4[(size_t)id * 32 + lane]);
                acc.x = fmaf(m, v.x, acc.x);
                acc.y = fmaf(m, v.y, acc.y);
                acc.z = fmaf(m, v.z, acc.z);
                acc.w = fmaf(m, v.w, acc.w);
            }
        }
        ((float4*)s_node)[w * 32 + lane] = acc;
        if (lane == 0) atomicAdd(&s_cnt, cnt);
    }

    {   // edge gather: warp w owns rows [w*8, w*8+8)
        float4 acc = make_float4(0.f, 0.f, 0.f, 0.f);
        #pragma unroll
        for (int q = 0; q < 8; ++q) {
            int k   = w * 8 + q;
            int eid = nbr_eid[b * K_ + k];
            float wk = w_final[k];
            float4 v = __ldg(&ef4[(size_t)eid * 32 + lane]);
            acc.x = fmaf(wk, v.x, acc.x);
            acc.y = fmaf(wk, v.y, acc.y);
            acc.z = fmaf(wk, v.z, acc.z);
            acc.w = fmaf(wk, v.w, acc.w);
        }
        ((float4*)s_edge)[w * 32 + lane] = acc;
    }
    __syncthreads();

    float* Sb = g_S + (size_t)b * SDP;
    {
        float a = 0.f, e = 0.f;
        #pragma unroll
        for (int q = 0; q < 4; ++q) {
            a += s_node[q * 128 + tid];
            e += s_edge[q * 128 + tid];
        }
        int c = s_cnt;
        float agg;
        if (c > 0) agg = a * (1.f / 1024.f) / (float)c;      // softmax -> exactly 1/c
        else       agg = node_raw[tid] * (1.f / 1024.f);
        float outn = agg + node_raw[(size_t)node_ids[b] * 128 + tid];
        Sb[CD_ + tid] = outn;
        Sb[tid]       = e;
    }
    if (tid < TD_) {
        float wt = time_w[tid], bt = time_b[tid];
        float acc = 0.f;
        #pragma unroll
        for (int k = 0; k < K_; ++k)
            acc = fmaf(s_wm[k], cosf(fmaf(s_dt[k], wt, bt)), acc);
        Sb[128 + tid] = acc;
    } else {
        Sb[256 + tid] = 0.f;    // S pad (harmless; Wcat pad rows are zero anyway)
    }
}

// ---------------------------------------------------------------------------
// Final: out[b,e] = cvec[e] + sum_i S[b,i]*Wcat[i,e].
// Grid 128 x 8 b-rows, 512 threads. Thread (e, rg, h): e = col, rg = row-quad,
// h = i-half [0,192)/[192,384). S staged row-interleaved so ld.shared.b64
// yields packed row-pairs for fma.rn.f32x2 (half the FMA issues).
// Wcat streamed per-half via 3-stage cp.async pipeline.
// ---------------------------------------------------------------------------
__global__ __launch_bounds__(512) void final_kernel(float* __restrict__ out)
{
    extern __shared__ float sm[];
    const int b0  = blockIdx.x * 8;
    const int tid = threadIdx.x;
    const int e   = tid & 127;
    const int rg  = (tid >> 7) & 1;    // row quad: rows 4rg..4rg+3
    const int h   = tid >> 8;          // i-half
    const int lt  = tid & 255;         // index within half

    // prologue: issue W stages 0,1 for this half
    #pragma unroll
    for (int s = 0; s < FST - 1; ++s) {
        const float4* src = ((const float4*)(g_Wcat + (h * 192 + s * FT2) * 128));
        float4* dst = (float4*)(sm + OFF_W + (h * FST + s) * (FT2 * 32) * 4);
        cp16(dst + lt,       src + lt);
        cp16(dst + lt + 256, src + lt + 256);
        CP_COMMIT();
    }

    // stage S row-interleaved: sp[h][il][rg*4 + r] = S[b0+4rg+r][h*192+il]
    #pragma unroll
    for (int x = 0; x < 6; ++x) {
        int idx = tid + x * 512;            // 0..3071
        int row = idx / 384;
        int i   = idx - row * 384;
        int hh  = (i >= 192) ? 1 : 0;
        int il  = i - hh * 192;
        float v = g_S[(size_t)(b0 + row) * SDP + i];
        sm[OFF_SP + hh * 1536 + il * 8 + (row >> 2) * 4 + (row & 3)] = v;
    }
    __syncthreads();

    ull acc_lo = 0, acc_hi = 0;        // rows (4rg+0,4rg+1) and (4rg+2,4rg+3)
    const float* spbase = sm + OFF_SP + h * 1536 + rg * 4;

    for (int t = 0; t < HNT; ++t) {
        CP_WAIT1();
        __syncthreads();               // stage t resident for all threads

        const float* wbuf = sm + OFF_W + (h * FST + (t % FST)) * (FT2 * 128);
        const int il0 = t * FT2;
        #pragma unroll
        for (int i = 0; i < FT2; ++i) {
            float wv = wbuf[i * 128 + e];
            ull  wp = pack2(wv, wv);
            const float* sp = spbase + (il0 + i) * 8;
            ull plo = *(const ull*)(sp);
            ull phi = *(const ull*)(sp + 2);
            acc_lo = fma2(plo, wp, acc_lo);
            acc_hi = fma2(phi, wp, acc_hi);
        }

        const int tn = t + FST - 1;
        if (tn < HNT) {
            const float4* src = ((const float4*)(g_Wcat + (h * 192 + tn * FT2) * 128));
            float4* dst = (float4*)(sm + OFF_W + (h * FST + (tn % FST)) * (FT2 * 128));
            cp16(dst + lt,       src + lt);
            cp16(dst + lt + 256, src + lt + 256);
            CP_COMMIT();
        } else {
            CP_COMMIT();               // keep group counts uniform
        }
    }

    // combine halves
    float r0, r1, r2, r3;
    unpack2(acc_lo, r0, r1);
    unpack2(acc_hi, r2, r3);
    float* part = sm + OFF_PART;
    __syncthreads();
    if (h == 1) {
        part[(4 * rg + 0) * 128 + e] = r0;
        part[(4 * rg + 1) * 128 + e] = r1;
        part[(4 * rg + 2) * 128 + e] = r2;
        part[(4 * rg + 3) * 128 + e] = r3;
    }
    __syncthreads();
    if (h == 0) {
        const float c0 = g_cvec[e];
        out[(size_t)(b0 + 4 * rg + 0) * 128 + e] = c0 + r0 + part[(4 * rg + 0) * 128 + e];
        out[(size_t)(b0 + 4 * rg + 1) * 128 + e] = c0 + r1 + part[(4 * rg + 1) * 128 + e];
        out[(size_t)(b0 + 4 * rg + 2) * 128 + e] = c0 + r2 + part[(4 * rg + 2) * 128 + e];
        out[(size_t)(b0 + 4 * rg + 3) * 128 + e] = c0 + r3 + part[(4 * rg + 3) * 128 + e];
    }
}

// ---------------------------------------------------------------------------
extern "C" void kernel_launch(void* const* d_in, const int* in_sizes, int n_in,
                              void* d_out, int out_size)
{
    const int*   node_ids = (const int*)  d_in[0];
    const float* node_it  = (const float*)d_in[1];
    const int*   nbr_nid  = (const int*)  d_in[2];
    const int*   nbr_eid  = (const int*)  d_in[3];
    const float* nbr_t    = (const float*)d_in[4];
    const int*   tg_ids   = (const int*)  d_in[5];
    const float* node_raw = (const float*)d_in[6];
    const float* edge_raw = (const float*)d_in[7];
    const float* time_w   = (const float*)d_in[8];
    const float* time_b   = (const float*)d_in[9];
    const float* W_edge   = (const float*)d_in[10];
    const float* b_edge   = (const float*)d_in[11];
    const float* w_final  = (const float*)d_in[12];
    const float* b_final  = (const float*)d_in[13];
    const float* W_node   = (const float*)d_in[14];
    const float* b_node   = (const float*)d_in[15];
    float* out = (float*)d_out;

    static int smem_set = 0;
    if (!smem_set) {
        cudaFuncSetAttribute(final_kernel,
                             cudaFuncAttributeMaxDynamicSharedMemorySize,
                             FSMEM_BYTES);
        smem_set = 1;
    }

    main_kernel<<<GRID_MAIN, 128>>>(node_ids, node_it, nbr_nid, nbr_eid, nbr_t,
                                    tg_ids, node_raw, edge_raw, time_w, time_b,
                                    w_final, W_edge, b_edge, b_final, W_node,
                                    b_node);
    final_kernel<<<B_ / 8, 512, FSMEM_BYTES>>>(out);
}

// round 10
// speedup vs baseline: 1.6424x; 1.0732x over previous
#include <cuda_runtime.h>
#include <cuda_bf16.h>
#include <math.h>
#include <cstdint>

// Shapes
#define B_  1024
#define K_  32
#define G_  1024
#define ND_ 128
#define ED_ 128
#define TD_ 100
#define CD_ 228
#define SD_ 356
#define SDP 384   // padded stride; Wcat rows [356,384) are zero
#define FT2 16    // final tile i-rows
#define HNT 12    // tiles per i-half (192/16)
#define FST 3     // cp.async stages per half

#define PREP_BLKS 74
#define GRID_MAIN (B_ + PREP_BLKS)

// final-kernel dynamic smem layout (floats)
#define OFF_W    0        // [2][3][16*128] = 12288 floats
#define OFF_SP   12288    // [2][192][4]    = 1536 floats (row-interleaved S)
#define OFF_PART 13824    // [4][128]       = 512 floats
#define FSMEM_FLOATS 14336
#define FSMEM_BYTES (FSMEM_FLOATS * 4)

__device__ __align__(16) float g_S[B_ * SDP];
__device__ __align__(16) float g_Wcat[SDP * ND_];
__device__ __align__(16) float g_cvec[ND_];

typedef unsigned long long ull;

// ---- packed f32x2 helpers -------------------------------------------------
__device__ __forceinline__ ull fma2(ull a, ull b, ull c) {
    ull d;
    asm("fma.rn.f32x2 %0, %1, %2, %3;" : "=l"(d) : "l"(a), "l"(b), "l"(c));
    return d;
}
__device__ __forceinline__ ull pack2(float lo, float hi) {
    ull d;
    asm("mov.b64 %0, {%1, %2};" : "=l"(d)
        : "r"(__float_as_uint(lo)), "r"(__float_as_uint(hi)));
    return d;
}
__device__ __forceinline__ void unpack2(ull v, float& lo, float& hi) {
    unsigned int a, b;
    asm("mov.b64 {%0, %1}, %2;" : "=r"(a), "=r"(b) : "l"(v));
    lo = __uint_as_float(a); hi = __uint_as_float(b);
}
// ---- cp.async helpers -----------------------------------------------------
__device__ __forceinline__ void cp16(void* smem_dst, const void* gsrc) {
    unsigned int s = (unsigned int)__cvta_generic_to_shared(smem_dst);
    asm volatile("cp.async.cg.shared.global [%0], [%1], 16;" :: "r"(s), "l"(gsrc));
}
#define CP_COMMIT() asm volatile("cp.async.commit_group;")
#define CP_WAIT1()  asm volatile("cp.async.wait_group 1;")

// ---------------------------------------------------------------------------
// Weight fold — trailing blocks of the main launch (hidden behind gathers).
// ---------------------------------------------------------------------------
__device__ __forceinline__ void prep_work(
    int blk, int e,
    const float* __restrict__ W_edge, const float* __restrict__ b_edge,
    const float* __restrict__ w_final, const float* __restrict__ b_final,
    const float* __restrict__ W_node, const float* __restrict__ b_node,
    float* s_we)
{
    if (blk < 57) {
        const int i0 = blk * 4;
        #pragma unroll
        for (int r = 0; r < 4; ++r)
            s_we[r * 128 + e] = W_edge[(i0 + r) * 128 + e];
        __syncthreads();
        float a0 = 0.f, a1 = 0.f, a2 = 0.f, a3 = 0.f;
        #pragma unroll 8
        for (int j = 0; j < 128; ++j) {
            float wn = __ldg(&W_node[j * 128 + e]);
            a0 = fmaf(s_we[0 * 128 + j], wn, a0);
            a1 = fmaf(s_we[1 * 128 + j], wn, a1);
            a2 = fmaf(s_we[2 * 128 + j], wn, a2);
            a3 = fmaf(s_we[3 * 128 + j], wn, a3);
        }
        g_Wcat[(i0 + 0) * 128 + e] = a0;
        g_Wcat[(i0 + 1) * 128 + e] = a1;
        g_Wcat[(i0 + 2) * 128 + e] = a2;
        g_Wcat[(i0 + 3) * 128 + e] = a3;
    } else if (blk < 73) {
        const int r0 = (blk - 57) * 8;
        #pragma unroll
        for (int r = 0; r < 8; ++r)
            g_Wcat[(CD_ + r0 + r) * 128 + e] = W_node[(128 + r0 + r) * 128 + e];
    } else {
        float sw = 0.f;
        #pragma unroll
        for (int k = 0; k < K_; ++k) sw += w_final[k];
        const float bf = b_final[0];
        float acc = b_node[e];
        #pragma unroll 8
        for (int j = 0; j < 128; ++j)
            acc = fmaf(fmaf(sw, b_edge[j], bf), __ldg(&W_node[j * 128 + e]), acc);
        g_cvec[e] = acc;
        #pragma unroll
        for (int r = SD_; r < SDP; ++r)       // keep pad rows zero
            g_Wcat[r * 128 + e] = 0.f;
    }
}

// ---------------------------------------------------------------------------
// Main kernel: blocks [0,1024) gather+reduce (LTS-bound, 512 MB);
// blocks [1024,1098) fold weights.
// Mask removed from the hot loop: Σ_{id>0} row[id] = Σ_all row[id] − nz·row[0].
// ---------------------------------------------------------------------------
__global__ __launch_bounds__(128) void main_kernel(
    const int*   __restrict__ node_ids,
    const float* __restrict__ node_it,
    const int*   __restrict__ nbr_nid,
    const int*   __restrict__ nbr_eid,
    const float* __restrict__ nbr_t,
    const int*   __restrict__ tg_ids,
    const float* __restrict__ node_raw,
    const float* __restrict__ edge_raw,
    const float* __restrict__ time_w,
    const float* __restrict__ time_b,
    const float* __restrict__ w_final,
    const float* __restrict__ W_edge,
    const float* __restrict__ b_edge,
    const float* __restrict__ b_final,
    const float* __restrict__ W_node,
    const float* __restrict__ b_node)
{
    __shared__ float s_node[4 * 128];
    __shared__ float s_edge[4 * 128];
    __shared__ float s_dt[K_];
    __shared__ float s_wm[K_];
    __shared__ int   s_cnt;

    const int b   = blockIdx.x;
    const int tid = threadIdx.x;

    if (b >= B_) {
        prep_work(b - B_, tid, W_edge, b_edge, w_final, b_final, W_node, b_node,
                  s_node);
        return;
    }

    const int w    = tid >> 5;
    const int lane = tid & 31;
    if (tid == 0) s_cnt = 0;
    if (tid < K_) {
        s_dt[tid] = node_it[b] - nbr_t[b * K_ + tid];
        s_wm[tid] = (nbr_nid[b * K_ + tid] == 0) ? 0.f : w_final[tid];
    }
    __syncthreads();

    const float4* nf4 = (const float4*)node_raw;
    const float4* ef4 = (const float4*)edge_raw;

    {   // node gather: warp w owns rows [w*256, w*256+256) — unmasked sum
        const int* tgb = tg_ids + b * G_ + w * 256;
        int myid[8];
        #pragma unroll
        for (int c = 0; c < 8; ++c)
            myid[c] = tgb[c * 32 + lane];

        float4 acc = make_float4(0.f, 0.f, 0.f, 0.f);
        int cnt = 0;
        #pragma unroll
        for (int c = 0; c < 8; ++c) {
            cnt += __popc(__ballot_sync(0xffffffffu, myid[c] > 0));
            #pragma unroll 16
            for (int r = 0; r < 32; ++r) {
                int id  = __shfl_sync(0xffffffffu, myid[c], r);
                float4 v = __ldg(&nf4[(size_t)id * 32 + lane]);
                acc.x += v.x; acc.y += v.y; acc.z += v.z; acc.w += v.w;
            }
        }
        ((float4*)s_node)[w * 32 + lane] = acc;
        if (lane == 0) atomicAdd(&s_cnt, cnt);
    }

    {   // edge gather: warp w owns rows [w*8, w*8+8)
        float4 acc = make_float4(0.f, 0.f, 0.f, 0.f);
        #pragma unroll
        for (int q = 0; q < 8; ++q) {
            int k   = w * 8 + q;
            int eid = nbr_eid[b * K_ + k];
            float wk = w_final[k];
            float4 v = __ldg(&ef4[(size_t)eid * 32 + lane]);
            acc.x = fmaf(wk, v.x, acc.x);
            acc.y = fmaf(wk, v.y, acc.y);
            acc.z = fmaf(wk, v.z, acc.z);
            acc.w = fmaf(wk, v.w, acc.w);
        }
        ((float4*)s_edge)[w * 32 + lane] = acc;
    }
    __syncthreads();

    float* Sb = g_S + (size_t)b * SDP;
    {
        float a = 0.f, e = 0.f;
        #pragma unroll
        for (int q = 0; q < 4; ++q) {
            a += s_node[q * 128 + tid];
            e += s_edge[q * 128 + tid];
        }
        int   c   = s_cnt;                 // # of id>0
        float r0v = node_raw[tid];         // row 0, element tid
        float agg;
        if (c > 0) {
            float am = a - (float)(G_ - c) * r0v;   // subtract masked rows (nz ~ 0)
            agg = am * (1.f / 1024.f) / (float)c;   // softmax -> exactly 1/c
        } else {
            agg = a * (1.f / (1024.f * 1024.f));    // all-masked: uniform scores
        }
        float outn = agg + node_raw[(size_t)node_ids[b] * 128 + tid];
        Sb[CD_ + tid] = outn;
        Sb[tid]       = e;
    }
    if (tid < TD_) {
        float wt = time_w[tid], bt = time_b[tid];
        float acc = 0.f;
        #pragma unroll
        for (int k = 0; k < K_; ++k)
            acc = fmaf(s_wm[k], cosf(fmaf(s_dt[k], wt, bt)), acc);
        Sb[128 + tid] = acc;
    } else {
        Sb[256 + tid] = 0.f;    // S pad
    }
}

// ---------------------------------------------------------------------------
// Final: out[b,e] = cvec[e] + sum_i S[b,i]*Wcat[i,e].
// Grid 256 x 4 b-rows, 256 threads (~2 CTA/SM). Thread (e, h): e = col,
// h = i-half. Each thread covers all 4 rows via 2 x fma.rn.f32x2 per i.
// Wcat streamed per-half via 3-stage cp.async pipeline of 16-row tiles.
// ---------------------------------------------------------------------------
__global__ __launch_bounds__(256) void final_kernel(float* __restrict__ out)
{
    extern __shared__ float sm[];
    const int b0  = blockIdx.x * 4;
    const int tid = threadIdx.x;
    const int e   = tid & 127;
    const int h   = tid >> 7;          // i-half [0,192)/[192,384)
    const int lt  = tid & 127;

    // prologue: issue W stages 0,1 for this half (tile = 512 float4, 4/thread)
    #pragma unroll
    for (int s = 0; s < FST - 1; ++s) {
        const float4* src = (const float4*)(g_Wcat + (h * 192 + s * FT2) * 128);
        float4* dst = (float4*)(sm + OFF_W + (h * FST + s) * (FT2 * 128));
        cp16(dst + lt,       src + lt);
        cp16(dst + lt + 128, src + lt + 128);
        cp16(dst + lt + 256, src + lt + 256);
        cp16(dst + lt + 384, src + lt + 384);
        CP_COMMIT();
    }

    // stage S row-interleaved: sp[hh][il][row] = S[b0+row][hh*192+il]
    #pragma unroll
    for (int x = 0; x < 6; ++x) {
        int idx = tid + x * 256;            // 0..1535
        int row = idx / 384;
        int i   = idx - row * 384;
        int hh  = (i >= 192) ? 1 : 0;
        int il  = i - hh * 192;
        sm[OFF_SP + hh * 768 + il * 4 + row] = g_S[(size_t)(b0 + row) * SDP + i];
    }
    __syncthreads();

    ull acc_lo = 0, acc_hi = 0;        // rows (0,1) and (2,3)
    const float* spbase = sm + OFF_SP + h * 768;

    for (int t = 0; t < HNT; ++t) {
        CP_WAIT1();
        __syncthreads();               // stage t resident for all threads

        const float* wbuf = sm + OFF_W + (h * FST + (t % FST)) * (FT2 * 128);
        const int il0 = t * FT2;
        #pragma unroll
        for (int i = 0; i < FT2; ++i) {
            float wv = wbuf[i * 128 + e];
            ull  wp = pack2(wv, wv);
            const float* sp = spbase + (il0 + i) * 4;
            ull plo = *(const ull*)(sp);
            ull phi = *(const ull*)(sp + 2);
            acc_lo = fma2(plo, wp, acc_lo);
            acc_hi = fma2(phi, wp, acc_hi);
        }

        const int tn = t + FST - 1;
        if (tn < HNT) {
            const float4* src = (const float4*)(g_Wcat + (h * 192 + tn * FT2) * 128);
            float4* dst = (float4*)(sm + OFF_W + (h * FST + (tn % FST)) * (FT2 * 128));
            cp16(dst + lt,       src + lt);
            cp16(dst + lt + 128, src + lt + 128);
            cp16(dst + lt + 256, src + lt + 256);
            cp16(dst + lt + 384, src + lt + 384);
            CP_COMMIT();
        } else {
            CP_COMMIT();               // keep group counts uniform
        }
    }

    // combine halves
    float r0, r1, r2, r3;
    unpack2(acc_lo, r0, r1);
    unpack2(acc_hi, r2, r3);
    float* part = sm + OFF_PART;
    __syncthreads();
    if (h == 1) {
        part[0 * 128 + e] = r0;
        part[1 * 128 + e] = r1;
        part[2 * 128 + e] = r2;
        part[3 * 128 + e] = r3;
    }
    __syncthreads();
    if (h == 0) {
        const float c0 = g_cvec[e];
        out[(size_t)(b0 + 0) * 128 + e] = c0 + r0 + part[0 * 128 + e];
        out[(size_t)(b0 + 1) * 128 + e] = c0 + r1 + part[1 * 128 + e];
        out[(size_t)(b0 + 2) * 128 + e] = c0 + r2 + part[2 * 128 + e];
        out[(size_t)(b0 + 3) * 128 + e] = c0 + r3 + part[3 * 128 + e];
    }
}

// ---------------------------------------------------------------------------
extern "C" void kernel_launch(void* const* d_in, const int* in_sizes, int n_in,
                              void* d_out, int out_size)
{
    const int*   node_ids = (const int*)  d_in[0];
    const float* node_it  = (const float*)d_in[1];
    const int*   nbr_nid  = (const int*)  d_in[2];
    const int*   nbr_eid  = (const int*)  d_in[3];
    const float* nbr_t    = (const float*)d_in[4];
    const int*   tg_ids   = (const int*)  d_in[5];
    const float* node_raw = (const float*)d_in[6];
    const float* edge_raw = (const float*)d_in[7];
    const float* time_w   = (const float*)d_in[8];
    const float* time_b   = (const float*)d_in[9];
    const float* W_edge   = (const float*)d_in[10];
    const float* b_edge   = (const float*)d_in[11];
    const float* w_final  = (const float*)d_in[12];
    const float* b_final  = (const float*)d_in[13];
    const float* W_node   = (const float*)d_in[14];
    const float* b_node   = (const float*)d_in[15];
    float* out = (float*)d_out;

    static int smem_set = 0;
    if (!smem_set) {
        cudaFuncSetAttribute(final_kernel,
                             cudaFuncAttributeMaxDynamicSharedMemorySize,
                             FSMEM_BYTES);
        smem_set = 1;
    }

    main_kernel<<<GRID_MAIN, 128>>>(node_ids, node_it, nbr_nid, nbr_eid, nbr_t,
                                    tg_ids, node_raw, edge_raw, time_w, time_b,
                                    w_final, W_edge, b_edge, b_final, W_node,
                                    b_node);
    final_kernel<<<B_ / 4, 256, FSMEM_BYTES>>>(out);
}